// round 10
// baseline (speedup 1.0000x reference)
#include <cuda_runtime.h>
#include <cuda_bf16.h>
#include <cstdint>

#define VJ 25
#define NBATCH 64
typedef __nv_bfloat16 bf16;

// ---------------- static device scratch ----------------
__device__ float g_X[30720000];                      // tconv fp32 outputs (n, m, C)
__device__ bf16  g_Hh[30720000], g_Hl[30720000];     // adjacency out, split bf16
__device__ bf16  g_Gh[61440000], g_Gl[61440000];     // mix out, split bf16
__device__ bf16  g_WSh[262144],  g_WSl[262144];      // split 1x1 weights [c][o]
__device__ bf16  g_WTh[2359296], g_WTl[2359296];     // split temporal weights [tap][i][o]

// ---------------- helpers ----------------
__device__ __forceinline__ uint32_t sptr(const void* p) {
    return (uint32_t)__cvta_generic_to_shared(p);
}
__device__ __forceinline__ void split2(float v, bf16& h, bf16& l) {
    h = __float2bfloat16(v);
    l = __float2bfloat16(v - __bfloat162float(h));
}
__device__ __forceinline__ void ldsm_x4(uint32_t* r, uint32_t addr) {
    asm volatile("ldmatrix.sync.aligned.m8n8.x4.shared.b16 {%0,%1,%2,%3}, [%4];"
                 : "=r"(r[0]), "=r"(r[1]), "=r"(r[2]), "=r"(r[3]) : "r"(addr));
}
__device__ __forceinline__ void ldsm_x4_t(uint32_t* r, uint32_t addr) {
    asm volatile("ldmatrix.sync.aligned.m8n8.x4.trans.shared.b16 {%0,%1,%2,%3}, [%4];"
                 : "=r"(r[0]), "=r"(r[1]), "=r"(r[2]), "=r"(r[3]) : "r"(addr));
}
__device__ __forceinline__ void mma16816(float* d, const uint32_t* a, const uint32_t* b) {
    asm volatile(
        "mma.sync.aligned.m16n8k16.row.col.f32.bf16.bf16.f32 "
        "{%0,%1,%2,%3}, {%4,%5,%6,%7}, {%8,%9}, {%0,%1,%2,%3};"
        : "+f"(d[0]), "+f"(d[1]), "+f"(d[2]), "+f"(d[3])
        : "r"(a[0]), "r"(a[1]), "r"(a[2]), "r"(a[3]), "r"(b[0]), "r"(b[1]));
}
__device__ __forceinline__ void cpasync16(uint32_t d, const void* g, int ok) {
    asm volatile("cp.async.cg.shared.global [%0], [%1], 16, %2;"
                 :: "r"(d), "l"(g), "r"(ok ? 16 : 0) : "memory");
}

// ---------------- fused weight split (ws + wt in one launch) ----------------
__global__ void split_both(const float* __restrict__ ws, const float* __restrict__ wt,
                           bf16* __restrict__ wsh, bf16* __restrict__ wsl,
                           bf16* __restrict__ wth, bf16* __restrict__ wtl,
                           int Cout, int Cin, int Kp) {
    int idx = blockIdx.x * 256 + threadIdx.x;
    int nws = Kp * Cout;
    if (idx < nws) {
        int c = idx / Cout, o = idx - c * Cout;
        float v = (c < Cin) ? ws[o * Cin + c] : 0.f;
        bf16 hh, ll; split2(v, hh, ll);
        wsh[idx] = hh; wsl[idx] = ll;
        return;
    }
    int j = idx - nws;
    if (j < 9 * Cout * Cout) {
        int k = j / (Cout * Cout);
        int r = j - k * Cout * Cout;
        int i = r / Cout, o = r - i * Cout;
        float v = wt[((size_t)o * Cout + i) * 9 + k];
        bf16 hh, ll; split2(v, hh, ll);
        wth[j] = hh; wtl[j] = ll;   // [(tap*C + i)*C + o]
    }
}

// ---------------- adjacency, scalar (layer 0: C=3, Kp=32) ----------------
__global__ void adj_kernel(const float* __restrict__ in, bf16* __restrict__ Hh,
                           bf16* __restrict__ Hl, const float* __restrict__ A,
                           int C, int Kp) {
    __shared__ float sA[VJ * VJ];
    __shared__ float sF[VJ * 256];
    const size_t bin = (size_t)blockIdx.x * VJ * C;
    const size_t bout = (size_t)blockIdx.x * VJ * Kp;
    for (int i = threadIdx.x; i < VJ * VJ; i += 256) sA[i] = A[i];
    const int tot = VJ * C;
    for (int i = threadIdx.x; i < tot; i += 256) sF[i] = in[bin + i];
    __syncthreads();
    const int outn = VJ * Kp;
    for (int i = threadIdx.x; i < outn; i += 256) {
        int w = i / Kp, c = i - w * Kp;
        float acc = 0.f;
        if (c < C) {
            #pragma unroll
            for (int v = 0; v < VJ; v++) acc = fmaf(sA[v * VJ + w], sF[v * C + c], acc);
        }
        bf16 hh, ll; split2(acc, hh, ll);
        Hh[bout + i] = hh; Hl[bout + i] = ll;
    }
}

// ---------------- adjacency, float4 vectorized (C==Kp, C%4==0) ----------------
__global__ void adj_kernel4(const float* __restrict__ in, bf16* __restrict__ Hh,
                            bf16* __restrict__ Hl, const float* __restrict__ A,
                            int C) {
    __shared__ float sA[VJ * VJ];
    __shared__ __align__(16) float sF[VJ * 256];
    const size_t base = (size_t)blockIdx.x * VJ * C;
    for (int i = threadIdx.x; i < VJ * VJ; i += 256) sA[i] = A[i];
    const int tot4 = VJ * C / 4;
    const float4* in4 = (const float4*)(in + base);
    float4* sF4 = (float4*)sF;
    for (int i = threadIdx.x; i < tot4; i += 256) sF4[i] = in4[i];
    __syncthreads();
    const int C4 = C >> 2;
    for (int i = threadIdx.x; i < VJ * C4; i += 256) {
        int w = i / C4, c4 = i - w * C4;
        float4 acc = make_float4(0.f, 0.f, 0.f, 0.f);
        #pragma unroll
        for (int v = 0; v < VJ; v++) {
            float a = sA[v * VJ + w];
            float4 f = sF4[v * C4 + c4];
            acc.x = fmaf(a, f.x, acc.x);
            acc.y = fmaf(a, f.y, acc.y);
            acc.z = fmaf(a, f.z, acc.z);
            acc.w = fmaf(a, f.w, acc.w);
        }
        bf16 h0, l0, h1, l1, h2, l2, h3, l3;
        split2(acc.x, h0, l0); split2(acc.y, h1, l1);
        split2(acc.z, h2, l2); split2(acc.w, h3, l3);
        size_t o = base + (size_t)w * C + c4 * 4;
        __nv_bfloat162 ph0; ph0.x = h0; ph0.y = h1;
        __nv_bfloat162 ph1; ph1.x = h2; ph1.y = h3;
        __nv_bfloat162 pl0; pl0.x = l0; pl0.y = l1;
        __nv_bfloat162 pl1; pl1.x = l2; pl1.y = l3;
        *(__nv_bfloat162*)(Hh + o) = ph0;
        *(__nv_bfloat162*)(Hh + o + 2) = ph1;
        *(__nv_bfloat162*)(Hl + o) = pl0;
        *(__nv_bfloat162*)(Hl + o + 2) = pl1;
    }
}

// ---------------- stride-1 tconv: 64x64 warp tiles (PROVEN, unchanged) ----------
template <int BM, int BN, int MODE_OUT>
__global__ void __launch_bounds__(128, 2) tconv_w64(
    const bf16* __restrict__ Ah, const bf16* __restrict__ Al,
    const bf16* __restrict__ Bh, const bf16* __restrict__ Bl,
    float* __restrict__ OutF, int M, int C, int Tout) {

    constexpr int WR = BM + 200;
    constexpr int APITCH = 24;
    constexpr int A_ST = WR * APITCH;
    constexpr int BPITCH = BN + 8;
    constexpr int B_ST = 16 * BPITCH;
    constexpr int WM = BM / 64;
    constexpr int BSEG = BN / 8;
    extern __shared__ __align__(128) bf16 smem[];
    bf16* aH = smem;
    bf16* aL = smem + A_ST;
    bf16* bB = smem + 2 * A_ST;

    const int tid = threadIdx.x;
    const int lane = tid & 31, wid = tid >> 5;
    const int wm = wid % WM, wn = wid / WM;
    const int m0 = blockIdx.x * BM;
    const int n0 = blockIdx.y * BN;
    const int bz = blockIdx.z;

    const bf16* An_h = Ah + (size_t)bz * M * C;
    const bf16* An_l = Al + (size_t)bz * M * C;

    float acc[4][8][4];
    #pragma unroll
    for (int a = 0; a < 4; a++)
        #pragma unroll
        for (int b = 0; b < 8; b++)
            #pragma unroll
            for (int c = 0; c < 4; c++) acc[a][b][c] = 0.f;

    const int nch = C >> 4;
    for (int ch = 0; ch < nch; ch++) {
        const int c0 = ch << 4;
        for (int idx = tid; idx < WR * 2; idx += 128) {
            int w = idx >> 1, seg = idx & 1;
            int flat = m0 - 100 + w;
            int ok = (flat >= 0 && flat < M);
            size_t g = ok ? ((size_t)flat * C + c0 + seg * 8) : 0;
            uint32_t d = sptr(aH + w * APITCH + seg * 8);
            cpasync16(d, An_h + g, ok);
            cpasync16(d + (uint32_t)(A_ST * 2), An_l + g, ok);
        }
        for (int idx = tid; idx < 9 * 16 * BSEG; idx += 128) {
            int tap = idx / (16 * BSEG);
            int r = idx - tap * 16 * BSEG;
            int row = r / BSEG, seg = r - row * BSEG;
            size_t o = ((size_t)(tap * C + c0 + row)) * C + n0 + seg * 8;
            uint32_t d = sptr(bB + tap * 2 * B_ST + row * BPITCH + seg * 8);
            cpasync16(d, Bh + o, 1);
            cpasync16(d + (uint32_t)(B_ST * 2), Bl + o, 1);
        }
        asm volatile("cp.async.commit_group;" ::: "memory");
        asm volatile("cp.async.wait_group 0;" ::: "memory");
        __syncthreads();

        for (int tap = 0; tap < 9; tap++) {
            const bf16* bH = bB + tap * 2 * B_ST;
            const bf16* bL = bH + B_ST;
            const int woff = 25 * tap;
            uint32_t ah[4][4], al[4][4], bh[8][2], bl[8][2];
            #pragma unroll
            for (int mt = 0; mt < 4; mt++) {
                int row = woff + wm * 64 + mt * 16 + (lane & 15);
                int col = (lane >> 4) * 8;
                ldsm_x4(ah[mt], sptr(aH + row * APITCH + col));
                ldsm_x4(al[mt], sptr(aL + row * APITCH + col));
            }
            #pragma unroll
            for (int np = 0; np < 4; np++) {
                uint32_t t0[4], t1[4];
                int krow = lane & 15;
                int col = wn * 64 + np * 16 + (lane >> 4) * 8;
                ldsm_x4_t(t0, sptr(bH + krow * BPITCH + col));
                ldsm_x4_t(t1, sptr(bL + krow * BPITCH + col));
                bh[np * 2][0] = t0[0]; bh[np * 2][1] = t0[1];
                bh[np * 2 + 1][0] = t0[2]; bh[np * 2 + 1][1] = t0[3];
                bl[np * 2][0] = t1[0]; bl[np * 2][1] = t1[1];
                bl[np * 2 + 1][0] = t1[2]; bl[np * 2 + 1][1] = t1[3];
            }
            #pragma unroll
            for (int mt = 0; mt < 4; mt++)
                #pragma unroll
                for (int nt = 0; nt < 8; nt++) {
                    mma16816(acc[mt][nt], ah[mt], bh[nt]);
                    mma16816(acc[mt][nt], ah[mt], bl[nt]);
                    mma16816(acc[mt][nt], al[mt], bh[nt]);
                }
        }
        __syncthreads();
    }

    const int rbase = m0 + wm * 64 + (lane >> 2);
    const int cbase = n0 + wn * 64 + 2 * (lane & 3);
    #pragma unroll
    for (int mt = 0; mt < 4; mt++) {
        #pragma unroll
        for (int half = 0; half < 2; half++) {
            int row = rbase + mt * 16 + half * 8;
            if (row >= M) continue;
            #pragma unroll
            for (int nt = 0; nt < 8; nt++) {
                int col = cbase + nt * 8;
                float x = fmaxf(acc[mt][nt][half * 2 + 0], 0.f);
                float y = fmaxf(acc[mt][nt][half * 2 + 1], 0.f);
                if (MODE_OUT == 1) {
                    float2 p = make_float2(x, y);
                    *(float2*)(OutF + ((size_t)bz * M + row) * C + col) = p;
                } else {
                    int t = row / VJ, v = row - t * VJ;
                    OutF[(((size_t)bz * C + col) * Tout + t) * VJ + v] = x;
                    OutF[(((size_t)bz * C + col + 1) * Tout + t) * VJ + v] = y;
                }
            }
        }
    }
}

// ---------------- unified 64x64-tile GEMM: mix (MODE_IN 0) + stride-2 tconv (MODE_IN 2) ----
// BK=16, 128 threads (4 warps, WM x WN = BM/64 x BN/64), 2 CTAs/SM.
// MODE_IN 0: A rows = m0+w, one "tap", nch = Ka/16. B = ws [k][o] (k-extent Ka, col-stride N).
// MODE_IN 2: stride-2 temporal conv; chunk = (tap, kchunk); A rows gathered per tap.
// MODE_OUT: 0 = relu + split-bf16 (OutH/OutL); 1 = relu fp32 [n][m][N].
template <int MODE_IN, int BM, int BN, int MODE_OUT>
__global__ void __launch_bounds__(128, 2) gemm64(
    const bf16* __restrict__ Ah, const bf16* __restrict__ Al,
    const bf16* __restrict__ Bh, const bf16* __restrict__ Bl,
    float* __restrict__ OutF, bf16* __restrict__ OutH, bf16* __restrict__ OutL,
    int M, int Ka, int N, int Tin) {

    constexpr int APITCH = 24;
    constexpr int A_ST = BM * APITCH;
    constexpr int BPITCH = BN + 8;
    constexpr int B_ST = 16 * BPITCH;
    constexpr int WM = BM / 64;
    constexpr int BSEG = BN / 8;
    extern __shared__ __align__(128) bf16 smem[];
    bf16* aH = smem;
    bf16* aL = smem + A_ST;
    bf16* bB = smem + 2 * A_ST;
    __shared__ int2 rinfo[BM];

    const int tid = threadIdx.x;
    const int lane = tid & 31, wid = tid >> 5;
    const int wm = wid % WM, wn = wid / WM;
    const int m0 = blockIdx.x * BM;
    const int n0 = blockIdx.y * BN;
    const int bz = blockIdx.z;

    const bf16* An_h = Ah;
    const bf16* An_l = Al;
    if (MODE_IN == 2) {
        size_t off = (size_t)bz * Tin * VJ * Ka;
        An_h += off; An_l += off;
        for (int w = tid; w < BM; w += 128) {
            int gm = m0 + w;
            int t = gm / VJ, v = gm - t * VJ;
            rinfo[w] = make_int2(gm < M ? t * 2 - 4 : -1000000, v);
        }
        __syncthreads();
    }

    float acc[4][8][4];
    #pragma unroll
    for (int a = 0; a < 4; a++)
        #pragma unroll
        for (int b = 0; b < 8; b++)
            #pragma unroll
            for (int c = 0; c < 4; c++) acc[a][b][c] = 0.f;

    const int kc = Ka >> 4;
    const int nch = (MODE_IN == 2) ? 9 * kc : kc;

    for (int ch = 0; ch < nch; ch++) {
        int tap = 0, c0;
        if (MODE_IN == 2) { tap = ch / kc; c0 = (ch - tap * kc) << 4; }
        else c0 = ch << 4;

        // ---- A tile (BM rows x 16 halves, hi/lo) ----
        for (int idx = tid; idx < BM * 2; idx += 128) {
            int w = idx >> 1, seg = idx & 1;
            int ok; size_t g = 0;
            if (MODE_IN == 0) {
                int gm = m0 + w;
                ok = gm < M;
                if (ok) g = (size_t)gm * Ka + c0 + seg * 8;
            } else {
                int2 ri = rinfo[w];
                int tin = ri.x + tap;
                ok = (tin >= 0 && tin < Tin);
                if (ok) g = ((size_t)tin * VJ + ri.y) * Ka + c0 + seg * 8;
            }
            uint32_t d = sptr(aH + w * APITCH + seg * 8);
            cpasync16(d, An_h + g, ok);
            cpasync16(d + (uint32_t)(A_ST * 2), An_l + g, ok);
        }
        // ---- B tile (16 x BN, hi/lo) ----
        for (int idx = tid; idx < 16 * BSEG; idx += 128) {
            int row = idx / BSEG, seg = idx - row * BSEG;
            size_t o = ((size_t)(tap * Ka + c0 + row)) * N + n0 + seg * 8;
            uint32_t d = sptr(bB + row * BPITCH + seg * 8);
            cpasync16(d, Bh + o, 1);
            cpasync16(d + (uint32_t)(B_ST * 2), Bl + o, 1);
        }
        asm volatile("cp.async.commit_group;" ::: "memory");
        asm volatile("cp.async.wait_group 0;" ::: "memory");
        __syncthreads();

        const bf16* bH = bB;
        const bf16* bL = bB + B_ST;
        uint32_t ah[4][4], al[4][4], bh[8][2], bl[8][2];
        #pragma unroll
        for (int mt = 0; mt < 4; mt++) {
            int row = wm * 64 + mt * 16 + (lane & 15);
            int col = (lane >> 4) * 8;
            ldsm_x4(ah[mt], sptr(aH + row * APITCH + col));
            ldsm_x4(al[mt], sptr(aL + row * APITCH + col));
        }
        #pragma unroll
        for (int np = 0; np < 4; np++) {
            uint32_t t0[4], t1[4];
            int krow = lane & 15;
            int col = wn * 64 + np * 16 + (lane >> 4) * 8;
            ldsm_x4_t(t0, sptr(bH + krow * BPITCH + col));
            ldsm_x4_t(t1, sptr(bL + krow * BPITCH + col));
            bh[np * 2][0] = t0[0]; bh[np * 2][1] = t0[1];
            bh[np * 2 + 1][0] = t0[2]; bh[np * 2 + 1][1] = t0[3];
            bl[np * 2][0] = t1[0]; bl[np * 2][1] = t1[1];
            bl[np * 2 + 1][0] = t1[2]; bl[np * 2 + 1][1] = t1[3];
        }
        #pragma unroll
        for (int mt = 0; mt < 4; mt++)
            #pragma unroll
            for (int nt = 0; nt < 8; nt++) {
                mma16816(acc[mt][nt], ah[mt], bh[nt]);
                mma16816(acc[mt][nt], ah[mt], bl[nt]);
                mma16816(acc[mt][nt], al[mt], bh[nt]);
            }
        __syncthreads();
    }

    // ---- epilogue ----
    const int rbase = m0 + wm * 64 + (lane >> 2);
    const int cbase = n0 + wn * 64 + 2 * (lane & 3);
    #pragma unroll
    for (int mt = 0; mt < 4; mt++) {
        #pragma unroll
        for (int half = 0; half < 2; half++) {
            int row = rbase + mt * 16 + half * 8;
            if (row >= M) continue;
            #pragma unroll
            for (int nt = 0; nt < 8; nt++) {
                int col = cbase + nt * 8;
                float x = fmaxf(acc[mt][nt][half * 2 + 0], 0.f);
                float y = fmaxf(acc[mt][nt][half * 2 + 1], 0.f);
                if (MODE_OUT == 0) {
                    bf16 hx, lx, hy, ly;
                    split2(x, hx, lx); split2(y, hy, ly);
                    __nv_bfloat162 ph; ph.x = hx; ph.y = hy;
                    __nv_bfloat162 pl2; pl2.x = lx; pl2.y = ly;
                    *(__nv_bfloat162*)(OutH + (size_t)row * N + col) = ph;
                    *(__nv_bfloat162*)(OutL + (size_t)row * N + col) = pl2;
                } else {
                    float2 p = make_float2(x, y);
                    *(float2*)(OutF + ((size_t)bz * M + row) * N + col) = p;
                }
            }
        }
    }
}

// ---------------- host orchestration ----------------
static inline int cdiv(int a, int b) { return (a + b - 1) / b; }

extern "C" void kernel_launch(void* const* d_in, const int* in_sizes, int n_in,
                              void* d_out, int out_size) {
    (void)out_size;
    const float* x = (const float*)d_in[0];
    const float* A = (const float*)d_in[1];

    bool interleaved = (n_in >= 4 && in_sizes[3] == 64 * 64 * 9);
    const float* ws[10];
    const float* wt[10];
    for (int i = 0; i < 10; i++) {
        if (interleaved) {
            ws[i] = (const float*)d_in[2 + 2 * i];
            wt[i] = (const float*)d_in[3 + 2 * i];
        } else {
            ws[i] = (const float*)d_in[2 + i];
            wt[i] = (const float*)d_in[12 + i];
        }
    }

    float* X;
    bf16 *Hh, *Hl, *Gh, *Gl, *WSh, *WSl, *WTh, *WTl;
    cudaGetSymbolAddress((void**)&X, g_X);
    cudaGetSymbolAddress((void**)&Hh, g_Hh);
    cudaGetSymbolAddress((void**)&Hl, g_Hl);
    cudaGetSymbolAddress((void**)&Gh, g_Gh);
    cudaGetSymbolAddress((void**)&Gl, g_Gl);
    cudaGetSymbolAddress((void**)&WSh, g_WSh);
    cudaGetSymbolAddress((void**)&WSl, g_WSl);
    cudaGetSymbolAddress((void**)&WTh, g_WTh);
    cudaGetSymbolAddress((void**)&WTl, g_WTl);

    const int Cin[10]  = {3, 64, 64, 64, 64, 128, 128, 128, 256, 256};
    const int Cout[10] = {64, 64, 64, 64, 128, 128, 128, 256, 256, 256};
    const int Tin[10]  = {300, 300, 300, 300, 300, 150, 150, 150, 75, 75};
    const int Tout[10] = {300, 300, 300, 300, 150, 150, 150, 75, 75, 75};
    const int S[10]    = {1, 1, 1, 1, 2, 1, 1, 2, 1, 1};
    const int Kp[10]   = {32, 64, 64, 64, 64, 128, 128, 128, 256, 256};

    int wsOff[10], wtOff[10];
    {
        int o = 0, o2 = 0;
        for (int i = 0; i < 10; i++) {
            wsOff[i] = o;  o  += Kp[i] * Cout[i];
            wtOff[i] = o2; o2 += 9 * Cout[i] * Cout[i];
        }
    }

    constexpr int SMEM_W64  = (2 * 456 * 24 + 18 * 16 * 72) * 2;              // 85248
    constexpr int SMEM_W128 = (2 * 328 * 24 + 18 * 16 * 136) * 2;             // 109824
    constexpr int SMEM_G256 = (2 * 256 * 24 + 2 * 16 * 72) * 2;               // 29184
    constexpr int SMEM_G128 = (2 * 128 * 24 + 2 * 16 * 136) * 2;              // 20992
    cudaFuncSetAttribute(tconv_w64<256, 64, 1>, cudaFuncAttributeMaxDynamicSharedMemorySize, SMEM_W64);
    cudaFuncSetAttribute(tconv_w64<128, 128, 1>, cudaFuncAttributeMaxDynamicSharedMemorySize, SMEM_W128);
    cudaFuncSetAttribute(tconv_w64<128, 128, 2>, cudaFuncAttributeMaxDynamicSharedMemorySize, SMEM_W128);

    auto do_split = [&](int i) {
        int tot = Kp[i] * Cout[i] + 9 * Cout[i] * Cout[i];
        split_both<<<cdiv(tot, 256), 256>>>(ws[i], wt[i],
                                            WSh + wsOff[i], WSl + wsOff[i],
                                            WTh + wtOff[i], WTl + wtOff[i],
                                            Cout[i], Cin[i], Kp[i]);
    };
    auto do_layer = [&](int i, const float* cur) {
        const int NT = NBATCH * Tin[i];
        if (i == 0)
            adj_kernel<<<NT, 256>>>(cur, Hh, Hl, A, Cin[i], Kp[i]);
        else
            adj_kernel4<<<NT, 256>>>(cur, Hh, Hl, A, Cin[i]);

        // channel mix + ReLU -> split bf16 G (64x64-tile kernel)
        const int M = NT * VJ;
        if (Cout[i] >= 128) {
            dim3 grid(cdiv(M, 128), Cout[i] / 128);
            gemm64<0, 128, 128, 0><<<grid, 128, SMEM_G128>>>(
                Hh, Hl, WSh + wsOff[i], WSl + wsOff[i],
                nullptr, Gh, Gl, M, Kp[i], Cout[i], 0);
        } else {
            dim3 grid(cdiv(M, 256), 1);
            gemm64<0, 256, 64, 0><<<grid, 128, SMEM_G256>>>(
                Hh, Hl, WSh + wsOff[i], WSl + wsOff[i],
                nullptr, Gh, Gl, M, Kp[i], Cout[i], 0);
        }

        // temporal conv + ReLU
        const int Mout = Tout[i] * VJ;
        if (S[i] == 1) {
            if (Cout[i] >= 128) {
                dim3 grid(cdiv(Mout, 128), Cout[i] / 128, NBATCH);
                if (i == 9)
                    tconv_w64<128, 128, 2><<<grid, 128, SMEM_W128>>>(
                        Gh, Gl, WTh + wtOff[i], WTl + wtOff[i], (float*)d_out,
                        Mout, Cout[i], Tout[i]);
                else
                    tconv_w64<128, 128, 1><<<grid, 128, SMEM_W128>>>(
                        Gh, Gl, WTh + wtOff[i], WTl + wtOff[i], X,
                        Mout, Cout[i], Tout[i]);
            } else {
                dim3 grid(cdiv(Mout, 256), 1, NBATCH);
                tconv_w64<256, 64, 1><<<grid, 128, SMEM_W64>>>(
                    Gh, Gl, WTh + wtOff[i], WTl + wtOff[i], X,
                    Mout, Cout[i], Tout[i]);
            }
        } else {
            // stride-2 temporal conv (64x64-tile, per-tap gather)
            dim3 grid(cdiv(Mout, 128), Cout[i] / 128, NBATCH);
            gemm64<2, 128, 128, 1><<<grid, 128, SMEM_G128>>>(
                Gh, Gl, WTh + wtOff[i], WTl + wtOff[i],
                X, nullptr, nullptr, Mout, Cout[i], Cout[i], Tin[i]);
        }
    };

    // Launch order: 0:split0  1:adj0  2:mix0  3:tconv0  (ncu captures idx 3)
    do_split(0);
    do_layer(0, x);
    for (int i = 1; i < 10; i++) do_split(i);
    for (int i = 1; i < 10; i++) do_layer(i, X);
}

// round 11
// speedup vs baseline: 1.0769x; 1.0769x over previous
#include <cuda_runtime.h>
#include <cuda_bf16.h>
#include <cstdint>

#define VJ 25
#define NBATCH 64
typedef __nv_bfloat16 bf16;

// ---------------- static device scratch ----------------
__device__ float g_X[30720000];                      // tconv fp32 outputs (n, m, C)
__device__ bf16  g_Hh[30720000], g_Hl[30720000];     // adjacency out, split bf16
__device__ bf16  g_Gh[61440000], g_Gl[61440000];     // mix out, split bf16
__device__ bf16  g_WSh[262144],  g_WSl[262144];      // split 1x1 weights [c][o]
__device__ bf16  g_WTh[2359296], g_WTl[2359296];     // split temporal weights [tap][i][o]

// ---------------- helpers ----------------
__device__ __forceinline__ uint32_t sptr(const void* p) {
    return (uint32_t)__cvta_generic_to_shared(p);
}
__device__ __forceinline__ void split2(float v, bf16& h, bf16& l) {
    h = __float2bfloat16(v);
    l = __float2bfloat16(v - __bfloat162float(h));
}
__device__ __forceinline__ void ldsm_x4(uint32_t* r, uint32_t addr) {
    asm volatile("ldmatrix.sync.aligned.m8n8.x4.shared.b16 {%0,%1,%2,%3}, [%4];"
                 : "=r"(r[0]), "=r"(r[1]), "=r"(r[2]), "=r"(r[3]) : "r"(addr));
}
__device__ __forceinline__ void ldsm_x4_t(uint32_t* r, uint32_t addr) {
    asm volatile("ldmatrix.sync.aligned.m8n8.x4.trans.shared.b16 {%0,%1,%2,%3}, [%4];"
                 : "=r"(r[0]), "=r"(r[1]), "=r"(r[2]), "=r"(r[3]) : "r"(addr));
}
__device__ __forceinline__ void mma16816(float* d, const uint32_t* a, const uint32_t* b) {
    asm volatile(
        "mma.sync.aligned.m16n8k16.row.col.f32.bf16.bf16.f32 "
        "{%0,%1,%2,%3}, {%4,%5,%6,%7}, {%8,%9}, {%0,%1,%2,%3};"
        : "+f"(d[0]), "+f"(d[1]), "+f"(d[2]), "+f"(d[3])
        : "r"(a[0]), "r"(a[1]), "r"(a[2]), "r"(a[3]), "r"(b[0]), "r"(b[1]));
}
__device__ __forceinline__ void cpasync16(uint32_t d, const void* g, int ok) {
    asm volatile("cp.async.cg.shared.global [%0], [%1], 16, %2;"
                 :: "r"(d), "l"(g), "r"(ok ? 16 : 0) : "memory");
}

// ---------------- fused weight split (ws + wt in one launch) ----------------
__global__ void split_both(const float* __restrict__ ws, const float* __restrict__ wt,
                           bf16* __restrict__ wsh, bf16* __restrict__ wsl,
                           bf16* __restrict__ wth, bf16* __restrict__ wtl,
                           int Cout, int Cin, int Kp) {
    int idx = blockIdx.x * 256 + threadIdx.x;
    int nws = Kp * Cout;
    if (idx < nws) {
        int c = idx / Cout, o = idx - c * Cout;
        float v = (c < Cin) ? ws[o * Cin + c] : 0.f;
        bf16 hh, ll; split2(v, hh, ll);
        wsh[idx] = hh; wsl[idx] = ll;
        return;
    }
    int j = idx - nws;
    if (j < 9 * Cout * Cout) {
        int k = j / (Cout * Cout);
        int r = j - k * Cout * Cout;
        int i = r / Cout, o = r - i * Cout;
        float v = wt[((size_t)o * Cout + i) * 9 + k];
        bf16 hh, ll; split2(v, hh, ll);
        wth[j] = hh; wtl[j] = ll;   // [(tap*C + i)*C + o]
    }
}

// ---------------- adjacency, scalar (layer 0: C=3, Kp=32) ----------------
__global__ void adj_kernel(const float* __restrict__ in, bf16* __restrict__ Hh,
                           bf16* __restrict__ Hl, const float* __restrict__ A,
                           int C, int Kp) {
    __shared__ float sA[VJ * VJ];
    __shared__ float sF[VJ * 256];
    const size_t bin = (size_t)blockIdx.x * VJ * C;
    const size_t bout = (size_t)blockIdx.x * VJ * Kp;
    for (int i = threadIdx.x; i < VJ * VJ; i += 256) sA[i] = A[i];
    const int tot = VJ * C;
    for (int i = threadIdx.x; i < tot; i += 256) sF[i] = in[bin + i];
    __syncthreads();
    const int outn = VJ * Kp;
    for (int i = threadIdx.x; i < outn; i += 256) {
        int w = i / Kp, c = i - w * Kp;
        float acc = 0.f;
        if (c < C) {
            #pragma unroll
            for (int v = 0; v < VJ; v++) acc = fmaf(sA[v * VJ + w], sF[v * C + c], acc);
        }
        bf16 hh, ll; split2(acc, hh, ll);
        Hh[bout + i] = hh; Hl[bout + i] = ll;
    }
}

// ---------------- adjacency, float4 vectorized (C==Kp, C%4==0) ----------------
__global__ void adj_kernel4(const float* __restrict__ in, bf16* __restrict__ Hh,
                            bf16* __restrict__ Hl, const float* __restrict__ A,
                            int C) {
    __shared__ float sA[VJ * VJ];
    __shared__ __align__(16) float sF[VJ * 256];
    const size_t base = (size_t)blockIdx.x * VJ * C;
    for (int i = threadIdx.x; i < VJ * VJ; i += 256) sA[i] = A[i];
    const int tot4 = VJ * C / 4;
    const float4* in4 = (const float4*)(in + base);
    float4* sF4 = (float4*)sF;
    for (int i = threadIdx.x; i < tot4; i += 256) sF4[i] = in4[i];
    __syncthreads();
    const int C4 = C >> 2;
    for (int i = threadIdx.x; i < VJ * C4; i += 256) {
        int w = i / C4, c4 = i - w * C4;
        float4 acc = make_float4(0.f, 0.f, 0.f, 0.f);
        #pragma unroll
        for (int v = 0; v < VJ; v++) {
            float a = sA[v * VJ + w];
            float4 f = sF4[v * C4 + c4];
            acc.x = fmaf(a, f.x, acc.x);
            acc.y = fmaf(a, f.y, acc.y);
            acc.z = fmaf(a, f.z, acc.z);
            acc.w = fmaf(a, f.w, acc.w);
        }
        bf16 h0, l0, h1, l1, h2, l2, h3, l3;
        split2(acc.x, h0, l0); split2(acc.y, h1, l1);
        split2(acc.z, h2, l2); split2(acc.w, h3, l3);
        size_t o = base + (size_t)w * C + c4 * 4;
        __nv_bfloat162 ph0; ph0.x = h0; ph0.y = h1;
        __nv_bfloat162 ph1; ph1.x = h2; ph1.y = h3;
        __nv_bfloat162 pl0; pl0.x = l0; pl0.y = l1;
        __nv_bfloat162 pl1; pl1.x = l2; pl1.y = l3;
        *(__nv_bfloat162*)(Hh + o) = ph0;
        *(__nv_bfloat162*)(Hh + o + 2) = ph1;
        *(__nv_bfloat162*)(Hl + o) = pl0;
        *(__nv_bfloat162*)(Hl + o + 2) = pl1;
    }
}

// ---------------- stride-1 tconv: 64x64 warp tiles (PROVEN, unchanged) ----------
template <int BM, int BN, int MODE_OUT>
__global__ void __launch_bounds__(128, 2) tconv_w64(
    const bf16* __restrict__ Ah, const bf16* __restrict__ Al,
    const bf16* __restrict__ Bh, const bf16* __restrict__ Bl,
    float* __restrict__ OutF, int M, int C, int Tout) {

    constexpr int WR = BM + 200;
    constexpr int APITCH = 24;
    constexpr int A_ST = WR * APITCH;
    constexpr int BPITCH = BN + 8;
    constexpr int B_ST = 16 * BPITCH;
    constexpr int WM = BM / 64;
    constexpr int BSEG = BN / 8;
    extern __shared__ __align__(128) bf16 smem[];
    bf16* aH = smem;
    bf16* aL = smem + A_ST;
    bf16* bB = smem + 2 * A_ST;

    const int tid = threadIdx.x;
    const int lane = tid & 31, wid = tid >> 5;
    const int wm = wid % WM, wn = wid / WM;
    const int m0 = blockIdx.x * BM;
    const int n0 = blockIdx.y * BN;
    const int bz = blockIdx.z;

    const bf16* An_h = Ah + (size_t)bz * M * C;
    const bf16* An_l = Al + (size_t)bz * M * C;

    float acc[4][8][4];
    #pragma unroll
    for (int a = 0; a < 4; a++)
        #pragma unroll
        for (int b = 0; b < 8; b++)
            #pragma unroll
            for (int c = 0; c < 4; c++) acc[a][b][c] = 0.f;

    const int nch = C >> 4;
    for (int ch = 0; ch < nch; ch++) {
        const int c0 = ch << 4;
        for (int idx = tid; idx < WR * 2; idx += 128) {
            int w = idx >> 1, seg = idx & 1;
            int flat = m0 - 100 + w;
            int ok = (flat >= 0 && flat < M);
            size_t g = ok ? ((size_t)flat * C + c0 + seg * 8) : 0;
            uint32_t d = sptr(aH + w * APITCH + seg * 8);
            cpasync16(d, An_h + g, ok);
            cpasync16(d + (uint32_t)(A_ST * 2), An_l + g, ok);
        }
        for (int idx = tid; idx < 9 * 16 * BSEG; idx += 128) {
            int tap = idx / (16 * BSEG);
            int r = idx - tap * 16 * BSEG;
            int row = r / BSEG, seg = r - row * BSEG;
            size_t o = ((size_t)(tap * C + c0 + row)) * C + n0 + seg * 8;
            uint32_t d = sptr(bB + tap * 2 * B_ST + row * BPITCH + seg * 8);
            cpasync16(d, Bh + o, 1);
            cpasync16(d + (uint32_t)(B_ST * 2), Bl + o, 1);
        }
        asm volatile("cp.async.commit_group;" ::: "memory");
        asm volatile("cp.async.wait_group 0;" ::: "memory");
        __syncthreads();

        for (int tap = 0; tap < 9; tap++) {
            const bf16* bH = bB + tap * 2 * B_ST;
            const bf16* bL = bH + B_ST;
            const int woff = 25 * tap;
            uint32_t ah[4][4], al[4][4], bh[8][2], bl[8][2];
            #pragma unroll
            for (int mt = 0; mt < 4; mt++) {
                int row = woff + wm * 64 + mt * 16 + (lane & 15);
                int col = (lane >> 4) * 8;
                ldsm_x4(ah[mt], sptr(aH + row * APITCH + col));
                ldsm_x4(al[mt], sptr(aL + row * APITCH + col));
            }
            #pragma unroll
            for (int np = 0; np < 4; np++) {
                uint32_t t0[4], t1[4];
                int krow = lane & 15;
                int col = wn * 64 + np * 16 + (lane >> 4) * 8;
                ldsm_x4_t(t0, sptr(bH + krow * BPITCH + col));
                ldsm_x4_t(t1, sptr(bL + krow * BPITCH + col));
                bh[np * 2][0] = t0[0]; bh[np * 2][1] = t0[1];
                bh[np * 2 + 1][0] = t0[2]; bh[np * 2 + 1][1] = t0[3];
                bl[np * 2][0] = t1[0]; bl[np * 2][1] = t1[1];
                bl[np * 2 + 1][0] = t1[2]; bl[np * 2 + 1][1] = t1[3];
            }
            #pragma unroll
            for (int mt = 0; mt < 4; mt++)
                #pragma unroll
                for (int nt = 0; nt < 8; nt++) {
                    mma16816(acc[mt][nt], ah[mt], bh[nt]);
                    mma16816(acc[mt][nt], ah[mt], bl[nt]);
                    mma16816(acc[mt][nt], al[mt], bh[nt]);
                }
        }
        __syncthreads();
    }

    const int rbase = m0 + wm * 64 + (lane >> 2);
    const int cbase = n0 + wn * 64 + 2 * (lane & 3);
    #pragma unroll
    for (int mt = 0; mt < 4; mt++) {
        #pragma unroll
        for (int half = 0; half < 2; half++) {
            int row = rbase + mt * 16 + half * 8;
            if (row >= M) continue;
            #pragma unroll
            for (int nt = 0; nt < 8; nt++) {
                int col = cbase + nt * 8;
                float x = fmaxf(acc[mt][nt][half * 2 + 0], 0.f);
                float y = fmaxf(acc[mt][nt][half * 2 + 1], 0.f);
                if (MODE_OUT == 1) {
                    float2 p = make_float2(x, y);
                    *(float2*)(OutF + ((size_t)bz * M + row) * C + col) = p;
                } else {
                    int t = row / VJ, v = row - t * VJ;
                    OutF[(((size_t)bz * C + col) * Tout + t) * VJ + v] = x;
                    OutF[(((size_t)bz * C + col + 1) * Tout + t) * VJ + v] = y;
                }
            }
        }
    }
}

// ---------------- unified 64x64-tile GEMM with 3-stage cp.async pipeline ----------
// mix (MODE_IN 0) + stride-2 tconv (MODE_IN 2). BK=16, 128 threads, 2 CTAs/SM.
// MODE_OUT: 0 = relu + split-bf16 (OutH/OutL); 1 = relu fp32 [n][m][N].
template <int MODE_IN, int BM, int BN, int MODE_OUT>
__global__ void __launch_bounds__(128, 2) gemm64(
    const bf16* __restrict__ Ah, const bf16* __restrict__ Al,
    const bf16* __restrict__ Bh, const bf16* __restrict__ Bl,
    float* __restrict__ OutF, bf16* __restrict__ OutH, bf16* __restrict__ OutL,
    int M, int Ka, int N, int Tin) {

    constexpr int STAGES = 3;
    constexpr int APITCH = 24;
    constexpr int A_ST = BM * APITCH;
    constexpr int BPITCH = BN + 8;
    constexpr int B_ST = 16 * BPITCH;
    constexpr int STG = 2 * A_ST + 2 * B_ST;
    constexpr int WM = BM / 64;
    constexpr int BSEG = BN / 8;
    extern __shared__ __align__(128) bf16 smem[];
    __shared__ int2 rinfo[BM];

    const int tid = threadIdx.x;
    const int lane = tid & 31, wid = tid >> 5;
    const int wm = wid % WM, wn = wid / WM;
    const int m0 = blockIdx.x * BM;
    const int n0 = blockIdx.y * BN;
    const int bz = blockIdx.z;

    const bf16* An_h = Ah;
    const bf16* An_l = Al;
    if (MODE_IN == 2) {
        size_t off = (size_t)bz * Tin * VJ * Ka;
        An_h += off; An_l += off;
        for (int w = tid; w < BM; w += 128) {
            int gm = m0 + w;
            int t = gm / VJ, v = gm - t * VJ;
            rinfo[w] = make_int2(gm < M ? t * 2 - 4 : -1000000, v);
        }
        __syncthreads();
    }

    float acc[4][8][4];
    #pragma unroll
    for (int a = 0; a < 4; a++)
        #pragma unroll
        for (int b = 0; b < 8; b++)
            #pragma unroll
            for (int c = 0; c < 4; c++) acc[a][b][c] = 0.f;

    const int kc = Ka >> 4;
    const int nch = (MODE_IN == 2) ? 9 * kc : kc;

    auto load_stage = [&](int s, int ch) {
        int tap = 0, c0;
        if (MODE_IN == 2) { tap = ch / kc; c0 = (ch - tap * kc) << 4; }
        else c0 = ch << 4;
        bf16* aH = smem + s * STG;
        bf16* bB = aH + 2 * A_ST;
        for (int idx = tid; idx < BM * 2; idx += 128) {
            int w = idx >> 1, seg = idx & 1;
            int ok; size_t g = 0;
            if (MODE_IN == 0) {
                int gm = m0 + w;
                ok = gm < M;
                if (ok) g = (size_t)gm * Ka + c0 + seg * 8;
            } else {
                int2 ri = rinfo[w];
                int tin = ri.x + tap;
                ok = (tin >= 0 && tin < Tin);
                if (ok) g = ((size_t)tin * VJ + ri.y) * Ka + c0 + seg * 8;
            }
            uint32_t d = sptr(aH + w * APITCH + seg * 8);
            cpasync16(d, An_h + g, ok);
            cpasync16(d + (uint32_t)(A_ST * 2), An_l + g, ok);
        }
        for (int idx = tid; idx < 16 * BSEG; idx += 128) {
            int row = idx / BSEG, seg = idx - row * BSEG;
            size_t o = ((size_t)(tap * Ka + c0 + row)) * N + n0 + seg * 8;
            uint32_t d = sptr(bB + row * BPITCH + seg * 8);
            cpasync16(d, Bh + o, 1);
            cpasync16(d + (uint32_t)(B_ST * 2), Bl + o, 1);
        }
    };

    // prologue: stages 0, 1
    #pragma unroll
    for (int s = 0; s < STAGES - 1; s++) {
        if (s < nch) load_stage(s, s);
        asm volatile("cp.async.commit_group;" ::: "memory");
    }

    for (int ch = 0; ch < nch; ch++) {
        asm volatile("cp.async.wait_group %0;" :: "n"(STAGES - 2) : "memory");
        __syncthreads();
        int pf = ch + STAGES - 1;
        if (pf < nch) load_stage(pf % STAGES, pf);
        asm volatile("cp.async.commit_group;" ::: "memory");

        const int s = ch % STAGES;
        const bf16* aH = smem + s * STG;
        const bf16* aL = aH + A_ST;
        const bf16* bH = aH + 2 * A_ST;
        const bf16* bL = bH + B_ST;
        uint32_t ah[4][4], al[4][4], bh[8][2], bl[8][2];
        #pragma unroll
        for (int mt = 0; mt < 4; mt++) {
            int row = wm * 64 + mt * 16 + (lane & 15);
            int col = (lane >> 4) * 8;
            ldsm_x4(ah[mt], sptr(aH + row * APITCH + col));
            ldsm_x4(al[mt], sptr(aL + row * APITCH + col));
        }
        #pragma unroll
        for (int np = 0; np < 4; np++) {
            uint32_t t0[4], t1[4];
            int krow = lane & 15;
            int col = wn * 64 + np * 16 + (lane >> 4) * 8;
            ldsm_x4_t(t0, sptr(bH + krow * BPITCH + col));
            ldsm_x4_t(t1, sptr(bL + krow * BPITCH + col));
            bh[np * 2][0] = t0[0]; bh[np * 2][1] = t0[1];
            bh[np * 2 + 1][0] = t0[2]; bh[np * 2 + 1][1] = t0[3];
            bl[np * 2][0] = t1[0]; bl[np * 2][1] = t1[1];
            bl[np * 2 + 1][0] = t1[2]; bl[np * 2 + 1][1] = t1[3];
        }
        #pragma unroll
        for (int mt = 0; mt < 4; mt++)
            #pragma unroll
            for (int nt = 0; nt < 8; nt++) {
                mma16816(acc[mt][nt], ah[mt], bh[nt]);
                mma16816(acc[mt][nt], ah[mt], bl[nt]);
                mma16816(acc[mt][nt], al[mt], bh[nt]);
            }
    }

    // ---- epilogue ----
    const int rbase = m0 + wm * 64 + (lane >> 2);
    const int cbase = n0 + wn * 64 + 2 * (lane & 3);
    #pragma unroll
    for (int mt = 0; mt < 4; mt++) {
        #pragma unroll
        for (int half = 0; half < 2; half++) {
            int row = rbase + mt * 16 + half * 8;
            if (row >= M) continue;
            #pragma unroll
            for (int nt = 0; nt < 8; nt++) {
                int col = cbase + nt * 8;
                float x = fmaxf(acc[mt][nt][half * 2 + 0], 0.f);
                float y = fmaxf(acc[mt][nt][half * 2 + 1], 0.f);
                if (MODE_OUT == 0) {
                    bf16 hx, lx, hy, ly;
                    split2(x, hx, lx); split2(y, hy, ly);
                    __nv_bfloat162 ph; ph.x = hx; ph.y = hy;
                    __nv_bfloat162 pl2; pl2.x = lx; pl2.y = ly;
                    *(__nv_bfloat162*)(OutH + (size_t)row * N + col) = ph;
                    *(__nv_bfloat162*)(OutL + (size_t)row * N + col) = pl2;
                } else {
                    float2 p = make_float2(x, y);
                    *(float2*)(OutF + ((size_t)bz * M + row) * N + col) = p;
                }
            }
        }
    }
}

// ---------------- host orchestration ----------------
static inline int cdiv(int a, int b) { return (a + b - 1) / b; }

extern "C" void kernel_launch(void* const* d_in, const int* in_sizes, int n_in,
                              void* d_out, int out_size) {
    (void)out_size;
    const float* x = (const float*)d_in[0];
    const float* A = (const float*)d_in[1];

    bool interleaved = (n_in >= 4 && in_sizes[3] == 64 * 64 * 9);
    const float* ws[10];
    const float* wt[10];
    for (int i = 0; i < 10; i++) {
        if (interleaved) {
            ws[i] = (const float*)d_in[2 + 2 * i];
            wt[i] = (const float*)d_in[3 + 2 * i];
        } else {
            ws[i] = (const float*)d_in[2 + i];
            wt[i] = (const float*)d_in[12 + i];
        }
    }

    float* X;
    bf16 *Hh, *Hl, *Gh, *Gl, *WSh, *WSl, *WTh, *WTl;
    cudaGetSymbolAddress((void**)&X, g_X);
    cudaGetSymbolAddress((void**)&Hh, g_Hh);
    cudaGetSymbolAddress((void**)&Hl, g_Hl);
    cudaGetSymbolAddress((void**)&Gh, g_Gh);
    cudaGetSymbolAddress((void**)&Gl, g_Gl);
    cudaGetSymbolAddress((void**)&WSh, g_WSh);
    cudaGetSymbolAddress((void**)&WSl, g_WSl);
    cudaGetSymbolAddress((void**)&WTh, g_WTh);
    cudaGetSymbolAddress((void**)&WTl, g_WTl);

    const int Cin[10]  = {3, 64, 64, 64, 64, 128, 128, 128, 256, 256};
    const int Cout[10] = {64, 64, 64, 64, 128, 128, 128, 256, 256, 256};
    const int Tin[10]  = {300, 300, 300, 300, 300, 150, 150, 150, 75, 75};
    const int Tout[10] = {300, 300, 300, 300, 150, 150, 150, 75, 75, 75};
    const int S[10]    = {1, 1, 1, 1, 2, 1, 1, 2, 1, 1};
    const int Kp[10]   = {32, 64, 64, 64, 64, 128, 128, 128, 256, 256};

    int wsOff[10], wtOff[10];
    {
        int o = 0, o2 = 0;
        for (int i = 0; i < 10; i++) {
            wsOff[i] = o;  o  += Kp[i] * Cout[i];
            wtOff[i] = o2; o2 += 9 * Cout[i] * Cout[i];
        }
    }

    constexpr int SMEM_W64  = (2 * 456 * 24 + 18 * 16 * 72) * 2;              // 85248
    constexpr int SMEM_W128 = (2 * 328 * 24 + 18 * 16 * 136) * 2;             // 109824
    constexpr int SMEM_G256 = 3 * (2 * 256 * 24 + 2 * 16 * 72) * 2;           // 87552
    constexpr int SMEM_G128 = 3 * (2 * 128 * 24 + 2 * 16 * 136) * 2;          // 62976
    cudaFuncSetAttribute(tconv_w64<256, 64, 1>, cudaFuncAttributeMaxDynamicSharedMemorySize, SMEM_W64);
    cudaFuncSetAttribute(tconv_w64<128, 128, 1>, cudaFuncAttributeMaxDynamicSharedMemorySize, SMEM_W128);
    cudaFuncSetAttribute(tconv_w64<128, 128, 2>, cudaFuncAttributeMaxDynamicSharedMemorySize, SMEM_W128);
    cudaFuncSetAttribute(gemm64<0, 128, 128, 0>, cudaFuncAttributeMaxDynamicSharedMemorySize, SMEM_G128);
    cudaFuncSetAttribute(gemm64<0, 256, 64, 0>, cudaFuncAttributeMaxDynamicSharedMemorySize, SMEM_G256);
    cudaFuncSetAttribute(gemm64<2, 128, 128, 1>, cudaFuncAttributeMaxDynamicSharedMemorySize, SMEM_G128);

    auto do_split = [&](int i) {
        int tot = Kp[i] * Cout[i] + 9 * Cout[i] * Cout[i];
        split_both<<<cdiv(tot, 256), 256>>>(ws[i], wt[i],
                                            WSh + wsOff[i], WSl + wsOff[i],
                                            WTh + wtOff[i], WTl + wtOff[i],
                                            Cout[i], Cin[i], Kp[i]);
    };
    auto do_layer = [&](int i, const float* cur) {
        const int NT = NBATCH * Tin[i];
        if (i == 0)
            adj_kernel<<<NT, 256>>>(cur, Hh, Hl, A, Cin[i], Kp[i]);
        else
            adj_kernel4<<<NT, 256>>>(cur, Hh, Hl, A, Cin[i]);

        // channel mix + ReLU -> split bf16 G (pipelined 64x64-tile kernel)
        const int M = NT * VJ;
        if (Cout[i] >= 128) {
            dim3 grid(cdiv(M, 128), Cout[i] / 128);
            gemm64<0, 128, 128, 0><<<grid, 128, SMEM_G128>>>(
                Hh, Hl, WSh + wsOff[i], WSl + wsOff[i],
                nullptr, Gh, Gl, M, Kp[i], Cout[i], 0);
        } else {
            dim3 grid(cdiv(M, 256), 1);
            gemm64<0, 256, 64, 0><<<grid, 128, SMEM_G256>>>(
                Hh, Hl, WSh + wsOff[i], WSl + wsOff[i],
                nullptr, Gh, Gl, M, Kp[i], Cout[i], 0);
        }

        // temporal conv + ReLU
        const int Mout = Tout[i] * VJ;
        if (S[i] == 1) {
            if (Cout[i] >= 128) {
                dim3 grid(cdiv(Mout, 128), Cout[i] / 128, NBATCH);
                if (i == 9)
                    tconv_w64<128, 128, 2><<<grid, 128, SMEM_W128>>>(
                        Gh, Gl, WTh + wtOff[i], WTl + wtOff[i], (float*)d_out,
                        Mout, Cout[i], Tout[i]);
                else
                    tconv_w64<128, 128, 1><<<grid, 128, SMEM_W128>>>(
                        Gh, Gl, WTh + wtOff[i], WTl + wtOff[i], X,
                        Mout, Cout[i], Tout[i]);
            } else {
                dim3 grid(cdiv(Mout, 256), 1, NBATCH);
                tconv_w64<256, 64, 1><<<grid, 128, SMEM_W64>>>(
                    Gh, Gl, WTh + wtOff[i], WTl + wtOff[i], X,
                    Mout, Cout[i], Tout[i]);
            }
        } else {
            // stride-2 temporal conv (pipelined 64x64-tile, per-tap gather)
            dim3 grid(cdiv(Mout, 128), Cout[i] / 128, NBATCH);
            gemm64<2, 128, 128, 1><<<grid, 128, SMEM_G128>>>(
                Gh, Gl, WTh + wtOff[i], WTl + wtOff[i],
                X, nullptr, nullptr, Mout, Cout[i], Cout[i], Tin[i]);
        }
    };

    // Launch order: 0:split0  1:adj0  2:mix0  3:tconv0  (ncu captures idx 3)
    do_split(0);
    do_layer(0, x);
    for (int i = 1; i < 10; i++) do_split(i);
    for (int i = 1; i < 10; i++) do_layer(i, X);
}

// round 13
// speedup vs baseline: 1.0999x; 1.0213x over previous
#include <cuda_runtime.h>
#include <cuda_bf16.h>
#include <cstdint>

#define VJ 25
#define NBATCH 64
typedef __nv_bfloat16 bf16;

// ---------------- static device scratch ----------------
__device__ float g_X[30720000];                      // tconv fp32 outputs (n, m, C)
__device__ bf16  g_Hh[30720000], g_Hl[30720000];     // adjacency out, split bf16
__device__ bf16  g_Gh[61440000], g_Gl[61440000];     // mix out, split bf16
__device__ bf16  g_WSh[262144],  g_WSl[262144];      // split 1x1 weights [c][o]
__device__ bf16  g_WTh[2359296], g_WTl[2359296];     // split temporal weights [tap][i][o]

// ---------------- helpers ----------------
__device__ __forceinline__ uint32_t sptr(const void* p) {
    return (uint32_t)__cvta_generic_to_shared(p);
}
__device__ __forceinline__ void split2(float v, bf16& h, bf16& l) {
    h = __float2bfloat16(v);
    l = __float2bfloat16(v - __bfloat162float(h));
}
__device__ __forceinline__ void ldsm_x4(uint32_t* r, uint32_t addr) {
    asm volatile("ldmatrix.sync.aligned.m8n8.x4.shared.b16 {%0,%1,%2,%3}, [%4];"
                 : "=r"(r[0]), "=r"(r[1]), "=r"(r[2]), "=r"(r[3]) : "r"(addr));
}
__device__ __forceinline__ void ldsm_x4_t(uint32_t* r, uint32_t addr) {
    asm volatile("ldmatrix.sync.aligned.m8n8.x4.trans.shared.b16 {%0,%1,%2,%3}, [%4];"
                 : "=r"(r[0]), "=r"(r[1]), "=r"(r[2]), "=r"(r[3]) : "r"(addr));
}
__device__ __forceinline__ void mma16816(float* d, const uint32_t* a, const uint32_t* b) {
    asm volatile(
        "mma.sync.aligned.m16n8k16.row.col.f32.bf16.bf16.f32 "
        "{%0,%1,%2,%3}, {%4,%5,%6,%7}, {%8,%9}, {%0,%1,%2,%3};"
        : "+f"(d[0]), "+f"(d[1]), "+f"(d[2]), "+f"(d[3])
        : "r"(a[0]), "r"(a[1]), "r"(a[2]), "r"(a[3]), "r"(b[0]), "r"(b[1]));
}
__device__ __forceinline__ void cpasync16(uint32_t d, const void* g, int ok) {
    asm volatile("cp.async.cg.shared.global [%0], [%1], 16, %2;"
                 :: "r"(d), "l"(g), "r"(ok ? 16 : 0) : "memory");
}

// ---------------- fused weight split ----------------
__global__ void split_both(const float* __restrict__ ws, const float* __restrict__ wt,
                           bf16* __restrict__ wsh, bf16* __restrict__ wsl,
                           bf16* __restrict__ wth, bf16* __restrict__ wtl,
                           int Cout, int Cin, int Kp) {
    int idx = blockIdx.x * 256 + threadIdx.x;
    int nws = Kp * Cout;
    if (idx < nws) {
        int c = idx / Cout, o = idx - c * Cout;
        float v = (c < Cin) ? ws[o * Cin + c] : 0.f;
        bf16 hh, ll; split2(v, hh, ll);
        wsh[idx] = hh; wsl[idx] = ll;
        return;
    }
    int j = idx - nws;
    if (j < 9 * Cout * Cout) {
        int k = j / (Cout * Cout);
        int r = j - k * Cout * Cout;
        int i = r / Cout, o = r - i * Cout;
        float v = wt[((size_t)o * Cout + i) * 9 + k];
        bf16 hh, ll; split2(v, hh, ll);
        wth[j] = hh; wtl[j] = ll;   // [(tap*C + i)*C + o]
    }
}

// ---------------- adjacency, scalar (layer 0) ----------------
__global__ void adj_kernel(const float* __restrict__ in, bf16* __restrict__ Hh,
                           bf16* __restrict__ Hl, const float* __restrict__ A,
                           int C, int Kp) {
    __shared__ float sA[VJ * VJ];
    __shared__ float sF[VJ * 256];
    const size_t bin = (size_t)blockIdx.x * VJ * C;
    const size_t bout = (size_t)blockIdx.x * VJ * Kp;
    for (int i = threadIdx.x; i < VJ * VJ; i += 256) sA[i] = A[i];
    const int tot = VJ * C;
    for (int i = threadIdx.x; i < tot; i += 256) sF[i] = in[bin + i];
    __syncthreads();
    const int outn = VJ * Kp;
    for (int i = threadIdx.x; i < outn; i += 256) {
        int w = i / Kp, c = i - w * Kp;
        float acc = 0.f;
        if (c < C) {
            #pragma unroll
            for (int v = 0; v < VJ; v++) acc = fmaf(sA[v * VJ + w], sF[v * C + c], acc);
        }
        bf16 hh, ll; split2(acc, hh, ll);
        Hh[bout + i] = hh; Hl[bout + i] = ll;
    }
}

// ---------------- adjacency, float4 vectorized ----------------
__global__ void adj_kernel4(const float* __restrict__ in, bf16* __restrict__ Hh,
                            bf16* __restrict__ Hl, const float* __restrict__ A,
                            int C) {
    __shared__ float sA[VJ * VJ];
    __shared__ __align__(16) float sF[VJ * 256];
    const size_t base = (size_t)blockIdx.x * VJ * C;
    for (int i = threadIdx.x; i < VJ * VJ; i += 256) sA[i] = A[i];
    const int tot4 = VJ * C / 4;
    const float4* in4 = (const float4*)(in + base);
    float4* sF4 = (float4*)sF;
    for (int i = threadIdx.x; i < tot4; i += 256) sF4[i] = in4[i];
    __syncthreads();
    const int C4 = C >> 2;
    for (int i = threadIdx.x; i < VJ * C4; i += 256) {
        int w = i / C4, c4 = i - w * C4;
        float4 acc = make_float4(0.f, 0.f, 0.f, 0.f);
        #pragma unroll
        for (int v = 0; v < VJ; v++) {
            float a = sA[v * VJ + w];
            float4 f = sF4[v * C4 + c4];
            acc.x = fmaf(a, f.x, acc.x);
            acc.y = fmaf(a, f.y, acc.y);
            acc.z = fmaf(a, f.z, acc.z);
            acc.w = fmaf(a, f.w, acc.w);
        }
        bf16 h0, l0, h1, l1, h2, l2, h3, l3;
        split2(acc.x, h0, l0); split2(acc.y, h1, l1);
        split2(acc.z, h2, l2); split2(acc.w, h3, l3);
        size_t o = base + (size_t)w * C + c4 * 4;
        __nv_bfloat162 ph0; ph0.x = h0; ph0.y = h1;
        __nv_bfloat162 ph1; ph1.x = h2; ph1.y = h3;
        __nv_bfloat162 pl0; pl0.x = l0; pl0.y = l1;
        __nv_bfloat162 pl1; pl1.x = l2; pl1.y = l3;
        *(__nv_bfloat162*)(Hh + o) = ph0;
        *(__nv_bfloat162*)(Hh + o + 2) = ph1;
        *(__nv_bfloat162*)(Hl + o) = pl0;
        *(__nv_bfloat162*)(Hl + o + 2) = pl1;
    }
}

// ---------------- stride-1 tconv: 64x64 warp tiles (PROVEN, unchanged) ----------
template <int BM, int BN, int MODE_OUT>
__global__ void __launch_bounds__(128, 2) tconv_w64(
    const bf16* __restrict__ Ah, const bf16* __restrict__ Al,
    const bf16* __restrict__ Bh, const bf16* __restrict__ Bl,
    float* __restrict__ OutF, int M, int C, int Tout) {

    constexpr int WR = BM + 200;
    constexpr int APITCH = 24;
    constexpr int A_ST = WR * APITCH;
    constexpr int BPITCH = BN + 8;
    constexpr int B_ST = 16 * BPITCH;
    constexpr int WM = BM / 64;
    constexpr int BSEG = BN / 8;
    extern __shared__ __align__(128) bf16 smem[];
    bf16* aH = smem;
    bf16* aL = smem + A_ST;
    bf16* bB = smem + 2 * A_ST;

    const int tid = threadIdx.x;
    const int lane = tid & 31, wid = tid >> 5;
    const int wm = wid % WM, wn = wid / WM;
    const int m0 = blockIdx.x * BM;
    const int n0 = blockIdx.y * BN;
    const int bz = blockIdx.z;

    const bf16* An_h = Ah + (size_t)bz * M * C;
    const bf16* An_l = Al + (size_t)bz * M * C;

    float acc[4][8][4];
    #pragma unroll
    for (int a = 0; a < 4; a++)
        #pragma unroll
        for (int b = 0; b < 8; b++)
            #pragma unroll
            for (int c = 0; c < 4; c++) acc[a][b][c] = 0.f;

    const int nch = C >> 4;
    for (int ch = 0; ch < nch; ch++) {
        const int c0 = ch << 4;
        for (int idx = tid; idx < WR * 2; idx += 128) {
            int w = idx >> 1, seg = idx & 1;
            int flat = m0 - 100 + w;
            int ok = (flat >= 0 && flat < M);
            size_t g = ok ? ((size_t)flat * C + c0 + seg * 8) : 0;
            uint32_t d = sptr(aH + w * APITCH + seg * 8);
            cpasync16(d, An_h + g, ok);
            cpasync16(d + (uint32_t)(A_ST * 2), An_l + g, ok);
        }
        for (int idx = tid; idx < 9 * 16 * BSEG; idx += 128) {
            int tap = idx / (16 * BSEG);
            int r = idx - tap * 16 * BSEG;
            int row = r / BSEG, seg = r - row * BSEG;
            size_t o = ((size_t)(tap * C + c0 + row)) * C + n0 + seg * 8;
            uint32_t d = sptr(bB + tap * 2 * B_ST + row * BPITCH + seg * 8);
            cpasync16(d, Bh + o, 1);
            cpasync16(d + (uint32_t)(B_ST * 2), Bl + o, 1);
        }
        asm volatile("cp.async.commit_group;" ::: "memory");
        asm volatile("cp.async.wait_group 0;" ::: "memory");
        __syncthreads();

        for (int tap = 0; tap < 9; tap++) {
            const bf16* bH = bB + tap * 2 * B_ST;
            const bf16* bL = bH + B_ST;
            const int woff = 25 * tap;
            uint32_t ah[4][4], al[4][4], bh[8][2], bl[8][2];
            #pragma unroll
            for (int mt = 0; mt < 4; mt++) {
                int row = woff + wm * 64 + mt * 16 + (lane & 15);
                int col = (lane >> 4) * 8;
                ldsm_x4(ah[mt], sptr(aH + row * APITCH + col));
                ldsm_x4(al[mt], sptr(aL + row * APITCH + col));
            }
            #pragma unroll
            for (int np = 0; np < 4; np++) {
                uint32_t t0[4], t1[4];
                int krow = lane & 15;
                int col = wn * 64 + np * 16 + (lane >> 4) * 8;
                ldsm_x4_t(t0, sptr(bH + krow * BPITCH + col));
                ldsm_x4_t(t1, sptr(bL + krow * BPITCH + col));
                bh[np * 2][0] = t0[0]; bh[np * 2][1] = t0[1];
                bh[np * 2 + 1][0] = t0[2]; bh[np * 2 + 1][1] = t0[3];
                bl[np * 2][0] = t1[0]; bl[np * 2][1] = t1[1];
                bl[np * 2 + 1][0] = t1[2]; bl[np * 2 + 1][1] = t1[3];
            }
            #pragma unroll
            for (int mt = 0; mt < 4; mt++)
                #pragma unroll
                for (int nt = 0; nt < 8; nt++) {
                    mma16816(acc[mt][nt], ah[mt], bh[nt]);
                    mma16816(acc[mt][nt], ah[mt], bl[nt]);
                    mma16816(acc[mt][nt], al[mt], bh[nt]);
                }
        }
        __syncthreads();
    }

    const int rbase = m0 + wm * 64 + (lane >> 2);
    const int cbase = n0 + wn * 64 + 2 * (lane & 3);
    #pragma unroll
    for (int mt = 0; mt < 4; mt++) {
        #pragma unroll
        for (int half = 0; half < 2; half++) {
            int row = rbase + mt * 16 + half * 8;
            if (row >= M) continue;
            #pragma unroll
            for (int nt = 0; nt < 8; nt++) {
                int col = cbase + nt * 8;
                float x = fmaxf(acc[mt][nt][half * 2 + 0], 0.f);
                float y = fmaxf(acc[mt][nt][half * 2 + 1], 0.f);
                if (MODE_OUT == 1) {
                    float2 p = make_float2(x, y);
                    *(float2*)(OutF + ((size_t)bz * M + row) * C + col) = p;
                } else {
                    int t = row / VJ, v = row - t * VJ;
                    OutF[(((size_t)bz * C + col) * Tout + t) * VJ + v] = x;
                    OutF[(((size_t)bz * C + col + 1) * Tout + t) * VJ + v] = y;
                }
            }
        }
    }
}

// ---------------- stride-2 tconv: window + per-lane ldsm row gather (fixed) ----------
// BM=250 output flat rows (exactly 10 temporal rows: 250 % 25 == 0, so t0 = m0/25
// exactly). Input window = contiguous flat rows [f0, f0+675), f0 = 2*m0 - 100.
// Output row r at tap k reads window row 50*(t-t0) + v + 25k (max 674). One window
// load per 16-wide K chunk serves all 9 taps. 4 warps of 64x64 tiles cover 256 rows;
// rows 250..255 are computed on dummy window row 0 and masked in the epilogue.
// APITCH=24 halves = 48 B rows (16 B-aligned cp.async). 2 CTAs/SM.
__global__ void __launch_bounds__(128, 2) tconv_s2w(
    const bf16* __restrict__ Ah, const bf16* __restrict__ Al,
    const bf16* __restrict__ Bh, const bf16* __restrict__ Bl,
    float* __restrict__ OutF, int Mout, int C, int Tin) {

    constexpr int BM = 250, BN = 64;
    constexpr int WR = 675;
    constexpr int APITCH = 24;
    constexpr int A_ST = WR * APITCH;
    constexpr int BPITCH = BN + 8;
    constexpr int B_ST = 16 * BPITCH;
    constexpr int BSEG = BN / 8;
    extern __shared__ __align__(128) bf16 smem[];
    bf16* aH = smem;
    bf16* aL = smem + A_ST;
    bf16* bB = smem + 2 * A_ST;
    __shared__ int rowmap[256];

    const int tid = threadIdx.x;
    const int lane = tid & 31, wid = tid >> 5;
    const int wm = wid;                     // WM=4, WN=1
    const int m0 = blockIdx.x * BM;
    const int n0 = blockIdx.y * BN;
    const int bz = blockIdx.z;
    const int Min = Tin * VJ;
    const int t0 = m0 / VJ;                 // exact (m0 % 25 == 0)
    const int f0 = 2 * m0 - 100;

    for (int r = tid; r < 256; r += 128) {
        int gm = m0 + r;
        int rmv = 0;
        if (r < BM && gm < Mout) {
            int t = gm / VJ, v = gm - t * VJ;
            rmv = 50 * (t - t0) + v;
        }
        rowmap[r] = rmv;
    }
    const bf16* An_h = Ah + (size_t)bz * Min * C;
    const bf16* An_l = Al + (size_t)bz * Min * C;
    __syncthreads();

    int rm[4];
    #pragma unroll
    for (int mt = 0; mt < 4; mt++)
        rm[mt] = rowmap[wm * 64 + mt * 16 + (lane & 15)];

    float acc[4][8][4];
    #pragma unroll
    for (int a = 0; a < 4; a++)
        #pragma unroll
        for (int b = 0; b < 8; b++)
            #pragma unroll
            for (int c = 0; c < 4; c++) acc[a][b][c] = 0.f;

    const int nch = C >> 4;
    for (int ch = 0; ch < nch; ch++) {
        const int c0 = ch << 4;
        // ---- A window ----
        for (int idx = tid; idx < WR * 2; idx += 128) {
            int w = idx >> 1, seg = idx & 1;
            int flat = f0 + w;
            int ok = (flat >= 0 && flat < Min);
            size_t g = ok ? ((size_t)flat * C + c0 + seg * 8) : 0;
            uint32_t d = sptr(aH + w * APITCH + seg * 8);
            cpasync16(d, An_h + g, ok);
            cpasync16(d + (uint32_t)(A_ST * 2), An_l + g, ok);
        }
        // ---- all 9 taps' B tiles ----
        for (int idx = tid; idx < 9 * 16 * BSEG; idx += 128) {
            int tap = idx / (16 * BSEG);
            int r = idx - tap * 16 * BSEG;
            int row = r / BSEG, seg = r - row * BSEG;
            size_t o = ((size_t)(tap * C + c0 + row)) * C + n0 + seg * 8;
            uint32_t d = sptr(bB + tap * 2 * B_ST + row * BPITCH + seg * 8);
            cpasync16(d, Bh + o, 1);
            cpasync16(d + (uint32_t)(B_ST * 2), Bl + o, 1);
        }
        asm volatile("cp.async.commit_group;" ::: "memory");
        asm volatile("cp.async.wait_group 0;" ::: "memory");
        __syncthreads();

        // ---- 9 taps, sync-free ----
        for (int tap = 0; tap < 9; tap++) {
            const bf16* bH = bB + tap * 2 * B_ST;
            const bf16* bL = bH + B_ST;
            const int woff = 25 * tap;
            uint32_t ah[4][4], al[4][4], bh[8][2], bl[8][2];
            #pragma unroll
            for (int mt = 0; mt < 4; mt++) {
                int row = rm[mt] + woff;
                int col = (lane >> 4) * 8;
                ldsm_x4(ah[mt], sptr(aH + row * APITCH + col));
                ldsm_x4(al[mt], sptr(aL + row * APITCH + col));
            }
            #pragma unroll
            for (int np = 0; np < 4; np++) {
                uint32_t t0r[4], t1r[4];
                int krow = lane & 15;
                int col = np * 16 + (lane >> 4) * 8;
                ldsm_x4_t(t0r, sptr(bH + krow * BPITCH + col));
                ldsm_x4_t(t1r, sptr(bL + krow * BPITCH + col));
                bh[np * 2][0] = t0r[0]; bh[np * 2][1] = t0r[1];
                bh[np * 2 + 1][0] = t0r[2]; bh[np * 2 + 1][1] = t0r[3];
                bl[np * 2][0] = t1r[0]; bl[np * 2][1] = t1r[1];
                bl[np * 2 + 1][0] = t1r[2]; bl[np * 2 + 1][1] = t1r[3];
            }
            #pragma unroll
            for (int mt = 0; mt < 4; mt++)
                #pragma unroll
                for (int nt = 0; nt < 8; nt++) {
                    mma16816(acc[mt][nt], ah[mt], bh[nt]);
                    mma16816(acc[mt][nt], ah[mt], bl[nt]);
                    mma16816(acc[mt][nt], al[mt], bh[nt]);
                }
        }
        __syncthreads();
    }

    // ---- epilogue: relu fp32 [n][m][C]; mask local row >= BM ----
    const int rbase = wm * 64 + (lane >> 2);
    const int cbase = n0 + 2 * (lane & 3);
    #pragma unroll
    for (int mt = 0; mt < 4; mt++) {
        #pragma unroll
        for (int half = 0; half < 2; half++) {
            int lr = rbase + mt * 16 + half * 8;
            int row = m0 + lr;
            if (lr >= BM || row >= Mout) continue;
            #pragma unroll
            for (int nt = 0; nt < 8; nt++) {
                int col = cbase + nt * 8;
                float x = fmaxf(acc[mt][nt][half * 2 + 0], 0.f);
                float y = fmaxf(acc[mt][nt][half * 2 + 1], 0.f);
                float2 p = make_float2(x, y);
                *(float2*)(OutF + ((size_t)bz * Mout + row) * C + col) = p;
            }
        }
    }
}

// ---------------- mix GEMM: 64x64 tiles, 3-stage cp.async pipeline (PROVEN) ----------
template <int BM, int BN>
__global__ void __launch_bounds__(128, 2) gemm64(
    const bf16* __restrict__ Ah, const bf16* __restrict__ Al,
    const bf16* __restrict__ Bh, const bf16* __restrict__ Bl,
    bf16* __restrict__ OutH, bf16* __restrict__ OutL,
    int M, int Ka, int N) {

    constexpr int STAGES = 3;
    constexpr int APITCH = 24;
    constexpr int A_ST = BM * APITCH;
    constexpr int BPITCH = BN + 8;
    constexpr int B_ST = 16 * BPITCH;
    constexpr int STG = 2 * A_ST + 2 * B_ST;
    constexpr int WM = BM / 64;
    constexpr int BSEG = BN / 8;
    extern __shared__ __align__(128) bf16 smem[];

    const int tid = threadIdx.x;
    const int lane = tid & 31, wid = tid >> 5;
    const int wm = wid % WM, wn = wid / WM;
    const int m0 = blockIdx.x * BM;
    const int n0 = blockIdx.y * BN;

    float acc[4][8][4];
    #pragma unroll
    for (int a = 0; a < 4; a++)
        #pragma unroll
        for (int b = 0; b < 8; b++)
            #pragma unroll
            for (int c = 0; c < 4; c++) acc[a][b][c] = 0.f;

    const int nch = Ka >> 4;

    auto load_stage = [&](int s, int ch) {
        int c0 = ch << 4;
        bf16* aH = smem + s * STG;
        bf16* bB = aH + 2 * A_ST;
        for (int idx = tid; idx < BM * 2; idx += 128) {
            int w = idx >> 1, seg = idx & 1;
            int gm = m0 + w;
            int ok = gm < M;
            size_t g = ok ? ((size_t)gm * Ka + c0 + seg * 8) : 0;
            uint32_t d = sptr(aH + w * APITCH + seg * 8);
            cpasync16(d, Ah + g, ok);
            cpasync16(d + (uint32_t)(A_ST * 2), Al + g, ok);
        }
        for (int idx = tid; idx < 16 * BSEG; idx += 128) {
            int row = idx / BSEG, seg = idx - row * BSEG;
            size_t o = ((size_t)(c0 + row)) * N + n0 + seg * 8;
            uint32_t d = sptr(bB + row * BPITCH + seg * 8);
            cpasync16(d, Bh + o, 1);
            cpasync16(d + (uint32_t)(B_ST * 2), Bl + o, 1);
        }
    };

    #pragma unroll
    for (int s = 0; s < STAGES - 1; s++) {
        if (s < nch) load_stage(s, s);
        asm volatile("cp.async.commit_group;" ::: "memory");
    }

    for (int ch = 0; ch < nch; ch++) {
        asm volatile("cp.async.wait_group %0;" :: "n"(STAGES - 2) : "memory");
        __syncthreads();
        int pf = ch + STAGES - 1;
        if (pf < nch) load_stage(pf % STAGES, pf);
        asm volatile("cp.async.commit_group;" ::: "memory");

        const int s = ch % STAGES;
        const bf16* aH = smem + s * STG;
        const bf16* aL = aH + A_ST;
        const bf16* bH = aH + 2 * A_ST;
        const bf16* bL = bH + B_ST;
        uint32_t ah[4][4], al[4][4], bh[8][2], bl[8][2];
        #pragma unroll
        for (int mt = 0; mt < 4; mt++) {
            int row = wm * 64 + mt * 16 + (lane & 15);
            int col = (lane >> 4) * 8;
            ldsm_x4(ah[mt], sptr(aH + row * APITCH + col));
            ldsm_x4(al[mt], sptr(aL + row * APITCH + col));
        }
        #pragma unroll
        for (int np = 0; np < 4; np++) {
            uint32_t t0[4], t1[4];
            int krow = lane & 15;
            int col = wn * 64 + np * 16 + (lane >> 4) * 8;
            ldsm_x4_t(t0, sptr(bH + krow * BPITCH + col));
            ldsm_x4_t(t1, sptr(bL + krow * BPITCH + col));
            bh[np * 2][0] = t0[0]; bh[np * 2][1] = t0[1];
            bh[np * 2 + 1][0] = t0[2]; bh[np * 2 + 1][1] = t0[3];
            bl[np * 2][0] = t1[0]; bl[np * 2][1] = t1[1];
            bl[np * 2 + 1][0] = t1[2]; bl[np * 2 + 1][1] = t1[3];
        }
        #pragma unroll
        for (int mt = 0; mt < 4; mt++)
            #pragma unroll
            for (int nt = 0; nt < 8; nt++) {
                mma16816(acc[mt][nt], ah[mt], bh[nt]);
                mma16816(acc[mt][nt], ah[mt], bl[nt]);
                mma16816(acc[mt][nt], al[mt], bh[nt]);
            }
    }

    // ---- epilogue: relu + split-bf16 ----
    const int rbase = m0 + wm * 64 + (lane >> 2);
    const int cbase = n0 + wn * 64 + 2 * (lane & 3);
    #pragma unroll
    for (int mt = 0; mt < 4; mt++) {
        #pragma unroll
        for (int half = 0; half < 2; half++) {
            int row = rbase + mt * 16 + half * 8;
            if (row >= M) continue;
            #pragma unroll
            for (int nt = 0; nt < 8; nt++) {
                int col = cbase + nt * 8;
                float x = fmaxf(acc[mt][nt][half * 2 + 0], 0.f);
                float y = fmaxf(acc[mt][nt][half * 2 + 1], 0.f);
                bf16 hx, lx, hy, ly;
                split2(x, hx, lx); split2(y, hy, ly);
                __nv_bfloat162 ph; ph.x = hx; ph.y = hy;
                __nv_bfloat162 pl2; pl2.x = lx; pl2.y = ly;
                *(__nv_bfloat162*)(OutH + (size_t)row * N + col) = ph;
                *(__nv_bfloat162*)(OutL + (size_t)row * N + col) = pl2;
            }
        }
    }
}

// ---------------- host orchestration ----------------
static inline int cdiv(int a, int b) { return (a + b - 1) / b; }

extern "C" void kernel_launch(void* const* d_in, const int* in_sizes, int n_in,
                              void* d_out, int out_size) {
    (void)out_size;
    const float* x = (const float*)d_in[0];
    const float* A = (const float*)d_in[1];

    bool interleaved = (n_in >= 4 && in_sizes[3] == 64 * 64 * 9);
    const float* ws[10];
    const float* wt[10];
    for (int i = 0; i < 10; i++) {
        if (interleaved) {
            ws[i] = (const float*)d_in[2 + 2 * i];
            wt[i] = (const float*)d_in[3 + 2 * i];
        } else {
            ws[i] = (const float*)d_in[2 + i];
            wt[i] = (const float*)d_in[12 + i];
        }
    }

    float* X;
    bf16 *Hh, *Hl, *Gh, *Gl, *WSh, *WSl, *WTh, *WTl;
    cudaGetSymbolAddress((void**)&X, g_X);
    cudaGetSymbolAddress((void**)&Hh, g_Hh);
    cudaGetSymbolAddress((void**)&Hl, g_Hl);
    cudaGetSymbolAddress((void**)&Gh, g_Gh);
    cudaGetSymbolAddress((void**)&Gl, g_Gl);
    cudaGetSymbolAddress((void**)&WSh, g_WSh);
    cudaGetSymbolAddress((void**)&WSl, g_WSl);
    cudaGetSymbolAddress((void**)&WTh, g_WTh);
    cudaGetSymbolAddress((void**)&WTl, g_WTl);

    const int Cin[10]  = {3, 64, 64, 64, 64, 128, 128, 128, 256, 256};
    const int Cout[10] = {64, 64, 64, 64, 128, 128, 128, 256, 256, 256};
    const int Tin[10]  = {300, 300, 300, 300, 300, 150, 150, 150, 75, 75};
    const int Tout[10] = {300, 300, 300, 300, 150, 150, 150, 75, 75, 75};
    const int S[10]    = {1, 1, 1, 1, 2, 1, 1, 2, 1, 1};
    const int Kp[10]   = {32, 64, 64, 64, 64, 128, 128, 128, 256, 256};

    int wsOff[10], wtOff[10];
    {
        int o = 0, o2 = 0;
        for (int i = 0; i < 10; i++) {
            wsOff[i] = o;  o  += Kp[i] * Cout[i];
            wtOff[i] = o2; o2 += 9 * Cout[i] * Cout[i];
        }
    }

    constexpr int SMEM_W64  = (2 * 456 * 24 + 18 * 16 * 72) * 2;              // 85248
    constexpr int SMEM_W128 = (2 * 328 * 24 + 18 * 16 * 136) * 2;             // 109824
    constexpr int SMEM_S2   = (2 * 675 * 24 + 18 * 16 * 72) * 2;              // 106272
    constexpr int SMEM_G256 = 3 * (2 * 256 * 24 + 2 * 16 * 72) * 2;           // 87552
    constexpr int SMEM_G128 = 3 * (2 * 128 * 24 + 2 * 16 * 136) * 2;          // 62976
    cudaFuncSetAttribute(tconv_w64<256, 64, 1>, cudaFuncAttributeMaxDynamicSharedMemorySize, SMEM_W64);
    cudaFuncSetAttribute(tconv_w64<128, 128, 1>, cudaFuncAttributeMaxDynamicSharedMemorySize, SMEM_W128);
    cudaFuncSetAttribute(tconv_w64<128, 128, 2>, cudaFuncAttributeMaxDynamicSharedMemorySize, SMEM_W128);
    cudaFuncSetAttribute(tconv_s2w, cudaFuncAttributeMaxDynamicSharedMemorySize, SMEM_S2);
    cudaFuncSetAttribute(gemm64<128, 128>, cudaFuncAttributeMaxDynamicSharedMemorySize, SMEM_G128);
    cudaFuncSetAttribute(gemm64<256, 64>, cudaFuncAttributeMaxDynamicSharedMemorySize, SMEM_G256);

    auto do_split = [&](int i) {
        int tot = Kp[i] * Cout[i] + 9 * Cout[i] * Cout[i];
        split_both<<<cdiv(tot, 256), 256>>>(ws[i], wt[i],
                                            WSh + wsOff[i], WSl + wsOff[i],
                                            WTh + wtOff[i], WTl + wtOff[i],
                                            Cout[i], Cin[i], Kp[i]);
    };
    auto do_layer = [&](int i, const float* cur) {
        const int NT = NBATCH * Tin[i];
        if (i == 0)
            adj_kernel<<<NT, 256>>>(cur, Hh, Hl, A, Cin[i], Kp[i]);
        else
            adj_kernel4<<<NT, 256>>>(cur, Hh, Hl, A, Cin[i]);

        // channel mix + ReLU -> split bf16 G
        const int M = NT * VJ;
        if (Cout[i] >= 128) {
            dim3 grid(cdiv(M, 128), Cout[i] / 128);
            gemm64<128, 128><<<grid, 128, SMEM_G128>>>(
                Hh, Hl, WSh + wsOff[i], WSl + wsOff[i], Gh, Gl, M, Kp[i], Cout[i]);
        } else {
            dim3 grid(cdiv(M, 256), 1);
            gemm64<256, 64><<<grid, 128, SMEM_G256>>>(
                Hh, Hl, WSh + wsOff[i], WSl + wsOff[i], Gh, Gl, M, Kp[i], Cout[i]);
        }

        // temporal conv + ReLU
        const int Mout = Tout[i] * VJ;
        if (S[i] == 1) {
            if (Cout[i] >= 128) {
                dim3 grid(cdiv(Mout, 128), Cout[i] / 128, NBATCH);
                if (i == 9)
                    tconv_w64<128, 128, 2><<<grid, 128, SMEM_W128>>>(
                        Gh, Gl, WTh + wtOff[i], WTl + wtOff[i], (float*)d_out,
                        Mout, Cout[i], Tout[i]);
                else
                    tconv_w64<128, 128, 1><<<grid, 128, SMEM_W128>>>(
                        Gh, Gl, WTh + wtOff[i], WTl + wtOff[i], X,
                        Mout, Cout[i], Tout[i]);
            } else {
                dim3 grid(cdiv(Mout, 256), 1, NBATCH);
                tconv_w64<256, 64, 1><<<grid, 128, SMEM_W64>>>(
                    Gh, Gl, WTh + wtOff[i], WTl + wtOff[i], X,
                    Mout, Cout[i], Tout[i]);
            }
        } else {
            // stride-2 tconv: windowed, per-lane ldsm row gather (BM=250)
            dim3 grid(cdiv(Mout, 250), Cout[i] / 64, NBATCH);
            tconv_s2w<<<grid, 128, SMEM_S2>>>(
                Gh, Gl, WTh + wtOff[i], WTl + wtOff[i],
                X, Mout, Cout[i], Tin[i]);
        }
    };

    // Launch order: 0:split0  1:adj0  2:mix0  3:tconv0  (ncu captures idx 3)
    do_split(0);
    do_layer(0, x);
    for (int i = 1; i < 10; i++) do_split(i);
    for (int i = 1; i < 10; i++) do_layer(i, X);
}